// round 6
// baseline (speedup 1.0000x reference)
#include <cuda_runtime.h>
#include <math.h>

#define NB      8192
#define TILE_B  32
#define NT      512
// header 272 | h@272(4096) x@4368(2048) z1@6416(8192) | z2@272 (aliases h,x) blog@8464 (inside dead z1)
#define OFF_H    272
#define OFF_X    4368
#define OFF_Z1   6416
#define OFF_Z2   272
#define OFF_BLOG 8464
#define SMEM_FLOATS 14608

__device__ __forceinline__ float silu_f(float x){
    return x * (1.0f / (1.0f + __expf(-x)));
}

// Warp-cooperative top-6 of 64 values (2 per lane). Tie-break: lower index.
__device__ __forceinline__ void topk6(float p0, float p1, int lane, int* sel, float* sv){
    #pragma unroll
    for (int t = 0; t < 6; ++t){
        float v = p0; int id = lane;
        if (p1 > v){ v = p1; id = lane + 32; }
        #pragma unroll
        for (int off = 16; off > 0; off >>= 1){
            float ov = __shfl_xor_sync(0xffffffffu, v, off);
            int  oid = __shfl_xor_sync(0xffffffffu, id, off);
            if (ov > v || (ov == v && oid < id)){ v = ov; id = oid; }
        }
        sv[t] = v; sel[t] = id;
        if (id == lane)           p0 = -INFINITY;
        else if (id == lane + 32) p1 = -INFINITY;
    }
}

// One row: gumbel perturb, top-5 select, one-hot write, exact-PL log-prob.
__device__ float row_topk_lp(const float* __restrict__ u,
                             const float* __restrict__ lg,
                             float m, float Z,
                             float* __restrict__ cfg,
                             int lane, int* selOut)
{
    float l0 = lg[lane], l1 = lg[lane + 32];
    float u0 = fmaxf(u[lane],      1e-10f);
    float u1 = fmaxf(u[lane + 32], 1e-10f);
    float p0 = l0 - __logf(-__logf(u0));
    float p1 = l1 - __logf(-__logf(u1));
    int sel[6]; float sv[6];
    topk6(p0, p1, lane, sel, sv);
    if (sv[4] - sv[5] < 1e-4f){
        p0 = l0 - (float)log(-log((double)u0));
        p1 = l1 - (float)log(-log((double)u1));
        topk6(p0, p1, lane, sel, sv);
    }
    float c0 = 0.f, c1 = 0.f;
    #pragma unroll
    for (int t = 0; t < 5; ++t){
        c0 += (sel[t] == lane)      ? 1.f : 0.f;
        c1 += (sel[t] == lane + 32) ? 1.f : 0.f;
    }
    cfg[lane]      = c0;
    cfg[lane + 32] = c1;

    // exact PL over 5! orderings via 2^5-subset DP
    float lsum = 0.f, e[5];
    #pragma unroll
    for (int t = 0; t < 5; ++t){
        float lt = lg[sel[t]];
        lsum += lt;
        e[t] = expf(lt - m);
    }
    float f[32];
    f[31] = 1.f;
    #pragma unroll
    for (int mask = 30; mask >= 0; --mask){
        float Em = 0.f, s = 0.f;
        #pragma unroll
        for (int t = 0; t < 5; ++t){
            if (mask & (1 << t)) Em += e[t];
            else                 s  += f[mask | (1 << t)];
        }
        f[mask] = __fdividef(s, Z - Em);
    }
    #pragma unroll
    for (int t = 0; t < 5; ++t) selOut[t] = sel[t];
    return lsum - 5.f * m + logf(f[0]);
}

__global__ __launch_bounds__(NT, 2)
void pcf_kernel(const float* __restrict__ Ua, const float* __restrict__ Ub,
                const float* __restrict__ AL,
                const float* __restrict__ W1, const float* __restrict__ b1,
                const float* __restrict__ W2, const float* __restrict__ b2,
                const float* __restrict__ V1, const float* __restrict__ c1,
                const float* __restrict__ V2, const float* __restrict__ c2,
                const float* __restrict__ V3, const float* __restrict__ c3,
                float* __restrict__ out)
{
    extern __shared__ float sm[];
    float* s_alog = sm;                    // 64
    float* s_scal = sm + 64;               // 4
    int*   s_sela = (int*)(sm + 68);       // 160
    float* s_lpa  = sm + 228;              // 32 -> header ends 272
    float* s_h    = sm + OFF_H;
    float* s_x    = sm + OFF_X;
    float* s_z1   = sm + OFF_Z1;
    float* s_z2   = sm + OFF_Z2;           // aliases h,x (dead by then)
    float* s_blog = sm + OFF_BLOG;         // inside dead z1

    const int tid  = threadIdx.x;
    const int lane = tid & 31;
    const int wid  = tid >> 5;             // 0..15
    const int row0 = blockIdx.x * TILE_B;

    // --- alpha logits stats (block-constant) ---
    if (wid == 0){
        float l0 = AL[lane], l1 = AL[lane + 32];
        s_alog[lane] = l0; s_alog[lane + 32] = l1;
        float mv = fmaxf(l0, l1);
        #pragma unroll
        for (int off = 16; off > 0; off >>= 1)
            mv = fmaxf(mv, __shfl_xor_sync(0xffffffffu, mv, off));
        float zv = expf(l0 - mv) + expf(l1 - mv);
        #pragma unroll
        for (int off = 16; off > 0; off >>= 1)
            zv += __shfl_xor_sync(0xffffffffu, zv, off);
        if (lane == 0){ s_scal[0] = mv; s_scal[1] = zv; }
    }
    __syncthreads();
    const float ma = s_scal[0], Za = s_scal[1];

    // --- alpha selection + lp_a (16 warps, 32 rows -> 2 rows/warp) ---
    for (int rr = 0; rr < 2; ++rr){
        int r = wid * 2 + rr;
        int row = row0 + r;
        int sel[5];
        float lp = row_topk_lp(Ua + (size_t)row * 64, s_alog, ma, Za,
                               out + (size_t)row * 128, lane, sel);
        if (lane == 0){
            s_lpa[r] = lp;
            #pragma unroll
            for (int t = 0; t < 5; ++t) s_sela[r * 5 + t] = sel[t];
        }
    }
    __syncthreads();

    // --- h = silu(sum of 5 W1 rows + b1) ---
    for (int i = tid; i < TILE_B * 128; i += NT){
        int r = i >> 7, j = i & 127;
        float a = b1[j];
        #pragma unroll
        for (int t = 0; t < 5; ++t) a += W1[s_sela[r * 5 + t] * 128 + j];
        s_h[i] = silu_f(a);
    }
    __syncthreads();

    // --- ctx = h @ W2 + b2  (K=128, N=64): 4 cols x 1 row per thread ---
    {
        const int cg = tid & 15, rg = tid >> 4;   // 16 col-groups x 32 rows
        const float* Wp = W2 + 4 * cg;
        float a0 = 0.f, a1 = 0.f, a2 = 0.f, a3 = 0.f;
        #pragma unroll 2
        for (int k = 0; k < 128; k += 4){
            float4 w0 = *(const float4*)(Wp + (k+0)*64);
            float4 w1 = *(const float4*)(Wp + (k+1)*64);
            float4 w2v = *(const float4*)(Wp + (k+2)*64);
            float4 w3 = *(const float4*)(Wp + (k+3)*64);
            const float4 h4 = *(const float4*)(s_h + rg*128 + k);
            a0 = fmaf(h4.x, w0.x, fmaf(h4.y, w1.x, fmaf(h4.z, w2v.x, fmaf(h4.w, w3.x, a0))));
            a1 = fmaf(h4.x, w0.y, fmaf(h4.y, w1.y, fmaf(h4.z, w2v.y, fmaf(h4.w, w3.y, a1))));
            a2 = fmaf(h4.x, w0.z, fmaf(h4.y, w1.z, fmaf(h4.z, w2v.z, fmaf(h4.w, w3.z, a2))));
            a3 = fmaf(h4.x, w0.w, fmaf(h4.y, w1.w, fmaf(h4.z, w2v.w, fmaf(h4.w, w3.w, a3))));
        }
        float4 bb = *(const float4*)(b2 + 4*cg);
        float4 o = make_float4(a0+bb.x, a1+bb.y, a2+bb.z, a3+bb.w);
        *(float4*)(s_x + rg*64 + 4*cg) = o;
    }
    __syncthreads();

    // --- z1 = silu(ctx @ V1[64:,:] + c1)  (K=64, N=256): 4 cols x 4 rows ---
    {
        const int cg = tid & 63, rg = tid >> 6;   // 64 col-groups, 8 row-groups x 4 rows
        const float* Vp = V1 + 64 * 256 + 4 * cg;
        float acc[4][4];
        #pragma unroll
        for (int r = 0; r < 4; r++)
            #pragma unroll
            for (int c = 0; c < 4; c++) acc[r][c] = 0.f;
        #pragma unroll 2
        for (int k = 0; k < 64; k += 4){
            float4 w0 = *(const float4*)(Vp + (k+0)*256);
            float4 w1 = *(const float4*)(Vp + (k+1)*256);
            float4 w2v = *(const float4*)(Vp + (k+2)*256);
            float4 w3 = *(const float4*)(Vp + (k+3)*256);
            #pragma unroll
            for (int r = 0; r < 4; r++){
                const float4 x4 = *(const float4*)(s_x + (rg*4 + r)*64 + k);
                acc[r][0] = fmaf(x4.x, w0.x, fmaf(x4.y, w1.x, fmaf(x4.z, w2v.x, fmaf(x4.w, w3.x, acc[r][0]))));
                acc[r][1] = fmaf(x4.x, w0.y, fmaf(x4.y, w1.y, fmaf(x4.z, w2v.y, fmaf(x4.w, w3.y, acc[r][1]))));
                acc[r][2] = fmaf(x4.x, w0.z, fmaf(x4.y, w1.z, fmaf(x4.z, w2v.z, fmaf(x4.w, w3.z, acc[r][2]))));
                acc[r][3] = fmaf(x4.x, w0.w, fmaf(x4.y, w1.w, fmaf(x4.z, w2v.w, fmaf(x4.w, w3.w, acc[r][3]))));
            }
        }
        float4 bb = *(const float4*)(c1 + 4*cg);
        #pragma unroll
        for (int r = 0; r < 4; r++){
            float4 o = make_float4(silu_f(acc[r][0]+bb.x), silu_f(acc[r][1]+bb.y),
                                   silu_f(acc[r][2]+bb.z), silu_f(acc[r][3]+bb.w));
            *(float4*)(s_z1 + (rg*4 + r)*256 + 4*cg) = o;
        }
    }
    __syncthreads();

    // --- z2 = silu(z1 @ V2 + c2)  (K=256, N=256): 4 cols x 4 rows ---
    {
        const int cg = tid & 63, rg = tid >> 6;
        const float* Vp = V2 + 4 * cg;
        float acc[4][4];
        #pragma unroll
        for (int r = 0; r < 4; r++)
            #pragma unroll
            for (int c = 0; c < 4; c++) acc[r][c] = 0.f;
        #pragma unroll 2
        for (int k = 0; k < 256; k += 4){
            float4 w0 = *(const float4*)(Vp + (k+0)*256);
            float4 w1 = *(const float4*)(Vp + (k+1)*256);
            float4 w2v = *(const float4*)(Vp + (k+2)*256);
            float4 w3 = *(const float4*)(Vp + (k+3)*256);
            #pragma unroll
            for (int r = 0; r < 4; r++){
                const float4 z4 = *(const float4*)(s_z1 + (rg*4 + r)*256 + k);
                acc[r][0] = fmaf(z4.x, w0.x, fmaf(z4.y, w1.x, fmaf(z4.z, w2v.x, fmaf(z4.w, w3.x, acc[r][0]))));
                acc[r][1] = fmaf(z4.x, w0.y, fmaf(z4.y, w1.y, fmaf(z4.z, w2v.y, fmaf(z4.w, w3.y, acc[r][1]))));
                acc[r][2] = fmaf(z4.x, w0.z, fmaf(z4.y, w1.z, fmaf(z4.z, w2v.z, fmaf(z4.w, w3.z, acc[r][2]))));
                acc[r][3] = fmaf(z4.x, w0.w, fmaf(z4.y, w1.w, fmaf(z4.z, w2v.w, fmaf(z4.w, w3.w, acc[r][3]))));
            }
        }
        float4 bb = *(const float4*)(c2 + 4*cg);
        #pragma unroll
        for (int r = 0; r < 4; r++){
            float4 o = make_float4(silu_f(acc[r][0]+bb.x), silu_f(acc[r][1]+bb.y),
                                   silu_f(acc[r][2]+bb.z), silu_f(acc[r][3]+bb.w));
            *(float4*)(s_z2 + (rg*4 + r)*256 + 4*cg) = o;
        }
    }
    __syncthreads();

    // --- beta_logits = z2 @ V3 + c3  (K=256, N=64): 4 cols x 1 row ---
    {
        const int cg = tid & 15, rg = tid >> 4;
        const float* Vp = V3 + 4 * cg;
        float a0 = 0.f, a1 = 0.f, a2 = 0.f, a3 = 0.f;
        #pragma unroll 2
        for (int k = 0; k < 256; k += 4){
            float4 w0 = *(const float4*)(Vp + (k+0)*64);
            float4 w1 = *(const float4*)(Vp + (k+1)*64);
            float4 w2v = *(const float4*)(Vp + (k+2)*64);
            float4 w3 = *(const float4*)(Vp + (k+3)*64);
            const float4 z4 = *(const float4*)(s_z2 + rg*256 + k);
            a0 = fmaf(z4.x, w0.x, fmaf(z4.y, w1.x, fmaf(z4.z, w2v.x, fmaf(z4.w, w3.x, a0))));
            a1 = fmaf(z4.x, w0.y, fmaf(z4.y, w1.y, fmaf(z4.z, w2v.y, fmaf(z4.w, w3.y, a1))));
            a2 = fmaf(z4.x, w0.z, fmaf(z4.y, w1.z, fmaf(z4.z, w2v.z, fmaf(z4.w, w3.z, a2))));
            a3 = fmaf(z4.x, w0.w, fmaf(z4.y, w1.w, fmaf(z4.z, w2v.w, fmaf(z4.w, w3.w, a3))));
        }
        float4 bb = *(const float4*)(c3 + 4*cg);
        float4 o = make_float4(a0+bb.x, a1+bb.y, a2+bb.z, a3+bb.w);
        *(float4*)(s_blog + rg*64 + 4*cg) = o;
    }
    __syncthreads();

    // --- beta selection + lp_b + final output ---
    for (int rr = 0; rr < 2; ++rr){
        int r = wid * 2 + rr;
        int row = row0 + r;
        const float* lg = s_blog + r * 64;
        float l0 = lg[lane], l1 = lg[lane + 32];
        float mv = fmaxf(l0, l1);
        #pragma unroll
        for (int off = 16; off > 0; off >>= 1)
            mv = fmaxf(mv, __shfl_xor_sync(0xffffffffu, mv, off));
        float zv = expf(l0 - mv) + expf(l1 - mv);
        #pragma unroll
        for (int off = 16; off > 0; off >>= 1)
            zv += __shfl_xor_sync(0xffffffffu, zv, off);
        int sel[5];
        float lpb = row_topk_lp(Ub + (size_t)row * 64, lg, mv, zv,
                                out + (size_t)row * 128 + 64, lane, sel);
        if (lane == 0)
            out[(size_t)NB * 128 + row] = s_lpa[r] + lpb;
    }
}

extern "C" void kernel_launch(void* const* d_in, const int* in_sizes, int n_in,
                              void* d_out, int out_size)
{
    (void)in_sizes; (void)n_in; (void)out_size;
    const float* Ua = (const float*)d_in[0];
    const float* Ub = (const float*)d_in[1];
    const float* AL = (const float*)d_in[2];
    const float* W1 = (const float*)d_in[3];
    const float* b1 = (const float*)d_in[4];
    const float* W2 = (const float*)d_in[5];
    const float* b2 = (const float*)d_in[6];
    const float* V1 = (const float*)d_in[7];
    const float* c1 = (const float*)d_in[8];
    const float* V2 = (const float*)d_in[9];
    const float* c2 = (const float*)d_in[10];
    const float* V3 = (const float*)d_in[11];
    const float* c3 = (const float*)d_in[12];
    float* out = (float*)d_out;

    const int smem_bytes = SMEM_FLOATS * (int)sizeof(float);
    cudaFuncSetAttribute(pcf_kernel, cudaFuncAttributeMaxDynamicSharedMemorySize, smem_bytes);
    pcf_kernel<<<NB / TILE_B, NT, smem_bytes>>>(Ua, Ub, AL, W1, b1, W2, b2,
                                                V1, c1, V2, c2, V3, c3, out);
}

// round 7
// speedup vs baseline: 1.0383x; 1.0383x over previous
#include <cuda_runtime.h>
#include <math.h>

#define NB      8192
#define TILE_B  16
#define NT      256
// header 272 | h@272(2048) x@2320(1024) z1@3344(4096) z2@7440(4096) | blog@272 (aliases dead h)
#define OFF_H    272
#define OFF_X    2320
#define OFF_Z1   3344
#define OFF_Z2   7440
#define OFF_BLOG 272
#define SMEM_FLOATS 11536

__device__ __forceinline__ float silu_f(float x){
    return x * (1.0f / (1.0f + __expf(-x)));
}

// Warp-cooperative top-6 of 64 values (2 per lane). Tie-break: lower index.
__device__ __forceinline__ void topk6(float p0, float p1, int lane, int* sel, float* sv){
    #pragma unroll
    for (int t = 0; t < 6; ++t){
        float v = p0; int id = lane;
        if (p1 > v){ v = p1; id = lane + 32; }
        #pragma unroll
        for (int off = 16; off > 0; off >>= 1){
            float ov = __shfl_xor_sync(0xffffffffu, v, off);
            int  oid = __shfl_xor_sync(0xffffffffu, id, off);
            if (ov > v || (ov == v && oid < id)){ v = ov; id = oid; }
        }
        sv[t] = v; sel[t] = id;
        if (id == lane)           p0 = -INFINITY;
        else if (id == lane + 32) p1 = -INFINITY;
    }
}

// One row: gumbel perturb, top-5 select, one-hot write, exact-PL log-prob.
__device__ float row_topk_lp(const float* __restrict__ u,
                             const float* __restrict__ lg,
                             float m, float Z,
                             float* __restrict__ cfg,
                             int lane, int* selOut)
{
    float l0 = lg[lane], l1 = lg[lane + 32];
    float u0 = fmaxf(u[lane],      1e-10f);
    float u1 = fmaxf(u[lane + 32], 1e-10f);
    float p0 = l0 - __logf(-__logf(u0));
    float p1 = l1 - __logf(-__logf(u1));
    int sel[6]; float sv[6];
    topk6(p0, p1, lane, sel, sv);
    if (sv[4] - sv[5] < 1e-4f){
        p0 = l0 - (float)log(-log((double)u0));
        p1 = l1 - (float)log(-log((double)u1));
        topk6(p0, p1, lane, sel, sv);
    }
    float c0 = 0.f, c1 = 0.f;
    #pragma unroll
    for (int t = 0; t < 5; ++t){
        c0 += (sel[t] == lane)      ? 1.f : 0.f;
        c1 += (sel[t] == lane + 32) ? 1.f : 0.f;
    }
    cfg[lane]      = c0;
    cfg[lane + 32] = c1;

    // exact PL over 5! orderings via 2^5-subset DP
    float lsum = 0.f, e[5];
    #pragma unroll
    for (int t = 0; t < 5; ++t){
        float lt = lg[sel[t]];
        lsum += lt;
        e[t] = expf(lt - m);
    }
    float f[32];
    f[31] = 1.f;
    #pragma unroll
    for (int mask = 30; mask >= 0; --mask){
        float Em = 0.f, s = 0.f;
        #pragma unroll
        for (int t = 0; t < 5; ++t){
            if (mask & (1 << t)) Em += e[t];
            else                 s  += f[mask | (1 << t)];
        }
        f[mask] = __fdividef(s, Z - Em);
    }
    #pragma unroll
    for (int t = 0; t < 5; ++t) selOut[t] = sel[t];
    return lsum - 5.f * m + logf(f[0]);
}

__global__ __launch_bounds__(NT, 4)
void pcf_kernel(const float* __restrict__ Ua, const float* __restrict__ Ub,
                const float* __restrict__ AL,
                const float* __restrict__ W1, const float* __restrict__ b1,
                const float* __restrict__ W2, const float* __restrict__ b2,
                const float* __restrict__ V1, const float* __restrict__ c1,
                const float* __restrict__ V2, const float* __restrict__ c2,
                const float* __restrict__ V3, const float* __restrict__ c3,
                float* __restrict__ out)
{
    extern __shared__ float sm[];
    float* s_alog = sm;                    // 64
    float* s_scal = sm + 64;               // 4
    int*   s_sela = (int*)(sm + 68);       // 80 (16 rows x 5)
    float* s_lpa  = sm + 148;              // 16 -> header ends 272
    float* s_h    = sm + OFF_H;
    float* s_x    = sm + OFF_X;
    float* s_z1   = sm + OFF_Z1;
    float* s_z2   = sm + OFF_Z2;
    float* s_blog = sm + OFF_BLOG;         // aliases dead h

    const int tid  = threadIdx.x;
    const int lane = tid & 31;
    const int wid  = tid >> 5;             // 0..7
    const int row0 = blockIdx.x * TILE_B;

    // --- alpha logits stats (block-constant) ---
    if (wid == 0){
        float l0 = AL[lane], l1 = AL[lane + 32];
        s_alog[lane] = l0; s_alog[lane + 32] = l1;
        float mv = fmaxf(l0, l1);
        #pragma unroll
        for (int off = 16; off > 0; off >>= 1)
            mv = fmaxf(mv, __shfl_xor_sync(0xffffffffu, mv, off));
        float zv = expf(l0 - mv) + expf(l1 - mv);
        #pragma unroll
        for (int off = 16; off > 0; off >>= 1)
            zv += __shfl_xor_sync(0xffffffffu, zv, off);
        if (lane == 0){ s_scal[0] = mv; s_scal[1] = zv; }
    }
    __syncthreads();
    const float ma = s_scal[0], Za = s_scal[1];

    // --- alpha selection + lp_a (8 warps, 16 rows -> 2 rows/warp) ---
    for (int rr = 0; rr < 2; ++rr){
        int r = wid * 2 + rr;
        int row = row0 + r;
        int sel[5];
        float lp = row_topk_lp(Ua + (size_t)row * 64, s_alog, ma, Za,
                               out + (size_t)row * 128, lane, sel);
        if (lane == 0){
            s_lpa[r] = lp;
            #pragma unroll
            for (int t = 0; t < 5; ++t) s_sela[r * 5 + t] = sel[t];
        }
    }
    __syncthreads();

    // --- h = silu(sum of 5 W1 rows + b1) ---
    for (int i = tid; i < TILE_B * 128; i += NT){
        int r = i >> 7, j = i & 127;
        float a = b1[j];
        #pragma unroll
        for (int t = 0; t < 5; ++t) a += W1[s_sela[r * 5 + t] * 128 + j];
        s_h[i] = silu_f(a);
    }
    __syncthreads();

    // --- ctx = h @ W2 + b2  (K=128, N=64): 4 cols x 1 row per thread ---
    {
        const int cg = tid & 15, rg = tid >> 4;   // 16 col-groups x 16 rows
        const float* Wp = W2 + 4 * cg;
        float a0 = 0.f, a1 = 0.f, a2 = 0.f, a3 = 0.f;
        #pragma unroll 2
        for (int k = 0; k < 128; k += 4){
            float4 w0 = *(const float4*)(Wp + (k+0)*64);
            float4 w1 = *(const float4*)(Wp + (k+1)*64);
            float4 w2v = *(const float4*)(Wp + (k+2)*64);
            float4 w3 = *(const float4*)(Wp + (k+3)*64);
            const float4 h4 = *(const float4*)(s_h + rg*128 + k);
            a0 = fmaf(h4.x, w0.x, fmaf(h4.y, w1.x, fmaf(h4.z, w2v.x, fmaf(h4.w, w3.x, a0))));
            a1 = fmaf(h4.x, w0.y, fmaf(h4.y, w1.y, fmaf(h4.z, w2v.y, fmaf(h4.w, w3.y, a1))));
            a2 = fmaf(h4.x, w0.z, fmaf(h4.y, w1.z, fmaf(h4.z, w2v.z, fmaf(h4.w, w3.z, a2))));
            a3 = fmaf(h4.x, w0.w, fmaf(h4.y, w1.w, fmaf(h4.z, w2v.w, fmaf(h4.w, w3.w, a3))));
        }
        float4 bb = *(const float4*)(b2 + 4*cg);
        float4 o = make_float4(a0+bb.x, a1+bb.y, a2+bb.z, a3+bb.w);
        *(float4*)(s_x + rg*64 + 4*cg) = o;
    }
    __syncthreads();

    // --- z1 = silu(ctx @ V1[64:,:] + c1)  (K=64, N=256): 4 cols x 4 rows ---
    {
        const int cg = tid & 63, rg = tid >> 6;   // 64 col-groups, 4 row-groups x 4 rows
        const float* Vp = V1 + 64 * 256 + 4 * cg;
        float acc[4][4];
        #pragma unroll
        for (int r = 0; r < 4; r++)
            #pragma unroll
            for (int c = 0; c < 4; c++) acc[r][c] = 0.f;
        #pragma unroll 2
        for (int k = 0; k < 64; k += 4){
            float4 w0 = *(const float4*)(Vp + (k+0)*256);
            float4 w1 = *(const float4*)(Vp + (k+1)*256);
            float4 w2v = *(const float4*)(Vp + (k+2)*256);
            float4 w3 = *(const float4*)(Vp + (k+3)*256);
            #pragma unroll
            for (int r = 0; r < 4; r++){
                const float4 x4 = *(const float4*)(s_x + (rg*4 + r)*64 + k);
                acc[r][0] = fmaf(x4.x, w0.x, fmaf(x4.y, w1.x, fmaf(x4.z, w2v.x, fmaf(x4.w, w3.x, acc[r][0]))));
                acc[r][1] = fmaf(x4.x, w0.y, fmaf(x4.y, w1.y, fmaf(x4.z, w2v.y, fmaf(x4.w, w3.y, acc[r][1]))));
                acc[r][2] = fmaf(x4.x, w0.z, fmaf(x4.y, w1.z, fmaf(x4.z, w2v.z, fmaf(x4.w, w3.z, acc[r][2]))));
                acc[r][3] = fmaf(x4.x, w0.w, fmaf(x4.y, w1.w, fmaf(x4.z, w2v.w, fmaf(x4.w, w3.w, acc[r][3]))));
            }
        }
        float4 bb = *(const float4*)(c1 + 4*cg);
        #pragma unroll
        for (int r = 0; r < 4; r++){
            float4 o = make_float4(silu_f(acc[r][0]+bb.x), silu_f(acc[r][1]+bb.y),
                                   silu_f(acc[r][2]+bb.z), silu_f(acc[r][3]+bb.w));
            *(float4*)(s_z1 + (rg*4 + r)*256 + 4*cg) = o;
        }
    }
    __syncthreads();

    // --- z2 = silu(z1 @ V2 + c2)  (K=256, N=256): 4 cols x 4 rows ---
    {
        const int cg = tid & 63, rg = tid >> 6;
        const float* Vp = V2 + 4 * cg;
        float acc[4][4];
        #pragma unroll
        for (int r = 0; r < 4; r++)
            #pragma unroll
            for (int c = 0; c < 4; c++) acc[r][c] = 0.f;
        #pragma unroll 2
        for (int k = 0; k < 256; k += 4){
            float4 w0 = *(const float4*)(Vp + (k+0)*256);
            float4 w1 = *(const float4*)(Vp + (k+1)*256);
            float4 w2v = *(const float4*)(Vp + (k+2)*256);
            float4 w3 = *(const float4*)(Vp + (k+3)*256);
            #pragma unroll
            for (int r = 0; r < 4; r++){
                const float4 z4 = *(const float4*)(s_z1 + (rg*4 + r)*256 + k);
                acc[r][0] = fmaf(z4.x, w0.x, fmaf(z4.y, w1.x, fmaf(z4.z, w2v.x, fmaf(z4.w, w3.x, acc[r][0]))));
                acc[r][1] = fmaf(z4.x, w0.y, fmaf(z4.y, w1.y, fmaf(z4.z, w2v.y, fmaf(z4.w, w3.y, acc[r][1]))));
                acc[r][2] = fmaf(z4.x, w0.z, fmaf(z4.y, w1.z, fmaf(z4.z, w2v.z, fmaf(z4.w, w3.z, acc[r][2]))));
                acc[r][3] = fmaf(z4.x, w0.w, fmaf(z4.y, w1.w, fmaf(z4.z, w2v.w, fmaf(z4.w, w3.w, acc[r][3]))));
            }
        }
        float4 bb = *(const float4*)(c2 + 4*cg);
        #pragma unroll
        for (int r = 0; r < 4; r++){
            float4 o = make_float4(silu_f(acc[r][0]+bb.x), silu_f(acc[r][1]+bb.y),
                                   silu_f(acc[r][2]+bb.z), silu_f(acc[r][3]+bb.w));
            *(float4*)(s_z2 + (rg*4 + r)*256 + 4*cg) = o;
        }
    }
    __syncthreads();

    // --- beta_logits = z2 @ V3 + c3  (K=256, N=64): 4 cols x 1 row ---
    {
        const int cg = tid & 15, rg = tid >> 4;
        const float* Vp = V3 + 4 * cg;
        float a0 = 0.f, a1 = 0.f, a2 = 0.f, a3 = 0.f;
        #pragma unroll 2
        for (int k = 0; k < 256; k += 4){
            float4 w0 = *(const float4*)(Vp + (k+0)*64);
            float4 w1 = *(const float4*)(Vp + (k+1)*64);
            float4 w2v = *(const float4*)(Vp + (k+2)*64);
            float4 w3 = *(const float4*)(Vp + (k+3)*64);
            const float4 z4 = *(const float4*)(s_z2 + rg*256 + k);
            a0 = fmaf(z4.x, w0.x, fmaf(z4.y, w1.x, fmaf(z4.z, w2v.x, fmaf(z4.w, w3.x, a0))));
            a1 = fmaf(z4.x, w0.y, fmaf(z4.y, w1.y, fmaf(z4.z, w2v.y, fmaf(z4.w, w3.y, a1))));
            a2 = fmaf(z4.x, w0.z, fmaf(z4.y, w1.z, fmaf(z4.z, w2v.z, fmaf(z4.w, w3.z, a2))));
            a3 = fmaf(z4.x, w0.w, fmaf(z4.y, w1.w, fmaf(z4.z, w2v.w, fmaf(z4.w, w3.w, a3))));
        }
        float4 bb = *(const float4*)(c3 + 4*cg);
        float4 o = make_float4(a0+bb.x, a1+bb.y, a2+bb.z, a3+bb.w);
        *(float4*)(s_blog + rg*64 + 4*cg) = o;
    }
    __syncthreads();

    // --- beta selection + lp_b + final output ---
    for (int rr = 0; rr < 2; ++rr){
        int r = wid * 2 + rr;
        int row = row0 + r;
        const float* lg = s_blog + r * 64;
        float l0 = lg[lane], l1 = lg[lane + 32];
        float mv = fmaxf(l0, l1);
        #pragma unroll
        for (int off = 16; off > 0; off >>= 1)
            mv = fmaxf(mv, __shfl_xor_sync(0xffffffffu, mv, off));
        float zv = expf(l0 - mv) + expf(l1 - mv);
        #pragma unroll
        for (int off = 16; off > 0; off >>= 1)
            zv += __shfl_xor_sync(0xffffffffu, zv, off);
        int sel[5];
        float lpb = row_topk_lp(Ub + (size_t)row * 64, lg, mv, zv,
                                out + (size_t)row * 128 + 64, lane, sel);
        if (lane == 0)
            out[(size_t)NB * 128 + row] = s_lpa[r] + lpb;
    }
}

extern "C" void kernel_launch(void* const* d_in, const int* in_sizes, int n_in,
                              void* d_out, int out_size)
{
    (void)in_sizes; (void)n_in; (void)out_size;
    const float* Ua = (const float*)d_in[0];
    const float* Ub = (const float*)d_in[1];
    const float* AL = (const float*)d_in[2];
    const float* W1 = (const float*)d_in[3];
    const float* b1 = (const float*)d_in[4];
    const float* W2 = (const float*)d_in[5];
    const float* b2 = (const float*)d_in[6];
    const float* V1 = (const float*)d_in[7];
    const float* c1 = (const float*)d_in[8];
    const float* V2 = (const float*)d_in[9];
    const float* c2 = (const float*)d_in[10];
    const float* V3 = (const float*)d_in[11];
    const float* c3 = (const float*)d_in[12];
    float* out = (float*)d_out;

    const int smem_bytes = SMEM_FLOATS * (int)sizeof(float);
    cudaFuncSetAttribute(pcf_kernel, cudaFuncAttributeMaxDynamicSharedMemorySize, smem_bytes);
    pcf_kernel<<<NB / TILE_B, NT, smem_bytes>>>(Ua, Ub, AL, W1, b1, W2, b2,
                                                V1, c1, V2, c2, V3, c3, out);
}

// round 8
// speedup vs baseline: 1.1532x; 1.1106x over previous
#include <cuda_runtime.h>
#include <math.h>

#define NB      8192
#define TILE_B  28
#define NT      256
#define GRID    293
// header: alog@0(64) scal@64(4) sela(int)@68(140) lpa@208(28) -> 240
#define OFF_H    240
#define OFF_X    3824
#define OFF_Z1   5616
#define OFF_Z2   12784
#define OFF_BLOG 19952
#define SMEM_FLOATS 21744

__device__ __forceinline__ float silu_f(float x){
    return x * (1.0f / (1.0f + __expf(-x)));
}

// Warp-cooperative top-6 of 64 values (2 per lane). Tie-break: lower index.
__device__ __forceinline__ void topk6(float p0, float p1, int lane, int* sel, float* sv){
    #pragma unroll
    for (int t = 0; t < 6; ++t){
        float v = p0; int id = lane;
        if (p1 > v){ v = p1; id = lane + 32; }
        #pragma unroll
        for (int off = 16; off > 0; off >>= 1){
            float ov = __shfl_xor_sync(0xffffffffu, v, off);
            int  oid = __shfl_xor_sync(0xffffffffu, id, off);
            if (ov > v || (ov == v && oid < id)){ v = ov; id = oid; }
        }
        sv[t] = v; sel[t] = id;
        if (id == lane)           p0 = -INFINITY;
        else if (id == lane + 32) p1 = -INFINITY;
    }
}

// One row: gumbel perturb, top-5 select, one-hot write, exact-PL log-prob.
__device__ float row_topk_lp(const float* __restrict__ u,
                             const float* __restrict__ lg,
                             float m, float Z,
                             float* __restrict__ cfg,
                             int lane, int* selOut)
{
    float l0 = lg[lane], l1 = lg[lane + 32];
    float u0 = fmaxf(u[lane],      1e-10f);
    float u1 = fmaxf(u[lane + 32], 1e-10f);
    float p0 = l0 - __logf(-__logf(u0));
    float p1 = l1 - __logf(-__logf(u1));
    int sel[6]; float sv[6];
    topk6(p0, p1, lane, sel, sv);
    if (sv[4] - sv[5] < 1e-4f){
        p0 = l0 - (float)log(-log((double)u0));
        p1 = l1 - (float)log(-log((double)u1));
        topk6(p0, p1, lane, sel, sv);
    }
    float c0 = 0.f, c1 = 0.f;
    #pragma unroll
    for (int t = 0; t < 5; ++t){
        c0 += (sel[t] == lane)      ? 1.f : 0.f;
        c1 += (sel[t] == lane + 32) ? 1.f : 0.f;
    }
    cfg[lane]      = c0;
    cfg[lane + 32] = c1;

    // exact PL over 5! orderings via 2^5-subset DP
    float lsum = 0.f, e[5];
    #pragma unroll
    for (int t = 0; t < 5; ++t){
        float lt = lg[sel[t]];
        lsum += lt;
        e[t] = expf(lt - m);
    }
    float f[32];
    f[31] = 1.f;
    #pragma unroll
    for (int mask = 30; mask >= 0; --mask){
        float Em = 0.f, s = 0.f;
        #pragma unroll
        for (int t = 0; t < 5; ++t){
            if (mask & (1 << t)) Em += e[t];
            else                 s  += f[mask | (1 << t)];
        }
        f[mask] = __fdividef(s, Z - Em);
    }
    #pragma unroll
    for (int t = 0; t < 5; ++t) selOut[t] = sel[t];
    return lsum - 5.f * m + logf(f[0]);
}

__global__ __launch_bounds__(NT, 2)
void pcf_kernel(const float* __restrict__ Ua, const float* __restrict__ Ub,
                const float* __restrict__ AL,
                const float* __restrict__ W1, const float* __restrict__ b1,
                const float* __restrict__ W2, const float* __restrict__ b2,
                const float* __restrict__ V1, const float* __restrict__ c1,
                const float* __restrict__ V2, const float* __restrict__ c2,
                const float* __restrict__ V3, const float* __restrict__ c3,
                float* __restrict__ out)
{
    extern __shared__ float sm[];
    float* s_alog = sm;                    // 64
    float* s_scal = sm + 64;               // 4
    int*   s_sela = (int*)(sm + 68);       // 140 (28 rows x 5)
    float* s_lpa  = sm + 208;              // 28 -> header ends 240
    float* s_h    = sm + OFF_H;            // 28x128
    float* s_x    = sm + OFF_X;            // 28x64
    float* s_z1   = sm + OFF_Z1;           // 28x256
    float* s_z2   = sm + OFF_Z2;           // 28x256
    float* s_blog = sm + OFF_BLOG;         // 28x64

    const int tid  = threadIdx.x;
    const int lane = tid & 31;
    const int wid  = tid >> 5;             // 0..7
    const int row0 = blockIdx.x * TILE_B;

    // --- alpha logits stats (block-constant) ---
    if (wid == 0){
        float l0 = AL[lane], l1 = AL[lane + 32];
        s_alog[lane] = l0; s_alog[lane + 32] = l1;
        float mv = fmaxf(l0, l1);
        #pragma unroll
        for (int off = 16; off > 0; off >>= 1)
            mv = fmaxf(mv, __shfl_xor_sync(0xffffffffu, mv, off));
        float zv = expf(l0 - mv) + expf(l1 - mv);
        #pragma unroll
        for (int off = 16; off > 0; off >>= 1)
            zv += __shfl_xor_sync(0xffffffffu, zv, off);
        if (lane == 0){ s_scal[0] = mv; s_scal[1] = zv; }
    }
    __syncthreads();
    const float ma = s_scal[0], Za = s_scal[1];

    // --- alpha selection + lp_a (8 warps x 4 slots, clamped to 28 rows) ---
    for (int rr = 0; rr < 4; ++rr){
        int rloc = wid * 4 + rr;
        if (rloc > TILE_B - 1) rloc = TILE_B - 1;          // duplicate work, identical values
        int row = row0 + rloc;
        if (row > NB - 1) row = NB - 1;                    // last-block clamp
        int sel[5];
        float lp = row_topk_lp(Ua + (size_t)row * 64, s_alog, ma, Za,
                               out + (size_t)row * 128, lane, sel);
        if (lane == 0){
            s_lpa[rloc] = lp;
            #pragma unroll
            for (int t = 0; t < 5; ++t) s_sela[rloc * 5 + t] = sel[t];
        }
    }
    __syncthreads();

    // --- h = silu(sum of 5 W1 rows + b1) ---
    for (int i = tid; i < TILE_B * 128; i += NT){
        int r = i >> 7, j = i & 127;
        float a = b1[j];
        #pragma unroll
        for (int t = 0; t < 5; ++t) a += W1[s_sela[r * 5 + t] * 128 + j];
        s_h[i] = silu_f(a);
    }
    __syncthreads();

    // --- ctx = h @ W2 + b2  (K=128, N=64): 4 cols x 2 rows (clamped) ---
    {
        const int cg = tid & 15, rg = tid >> 4;   // 16 col-groups, 16 row-groups
        const float* Wp = W2 + 4 * cg;
        int r0 = rg * 2;     if (r0 > TILE_B - 1) r0 = TILE_B - 1;
        int r1 = rg * 2 + 1; if (r1 > TILE_B - 1) r1 = TILE_B - 1;
        float acc[2][4];
        #pragma unroll
        for (int r = 0; r < 2; r++)
            #pragma unroll
            for (int c = 0; c < 4; c++) acc[r][c] = 0.f;
        #pragma unroll 2
        for (int k = 0; k < 128; k += 4){
            float4 w0 = *(const float4*)(Wp + (k+0)*64);
            float4 w1 = *(const float4*)(Wp + (k+1)*64);
            float4 w2v = *(const float4*)(Wp + (k+2)*64);
            float4 w3 = *(const float4*)(Wp + (k+3)*64);
            const float4 h0 = *(const float4*)(s_h + r0*128 + k);
            const float4 h1 = *(const float4*)(s_h + r1*128 + k);
            acc[0][0] = fmaf(h0.x, w0.x, fmaf(h0.y, w1.x, fmaf(h0.z, w2v.x, fmaf(h0.w, w3.x, acc[0][0]))));
            acc[0][1] = fmaf(h0.x, w0.y, fmaf(h0.y, w1.y, fmaf(h0.z, w2v.y, fmaf(h0.w, w3.y, acc[0][1]))));
            acc[0][2] = fmaf(h0.x, w0.z, fmaf(h0.y, w1.z, fmaf(h0.z, w2v.z, fmaf(h0.w, w3.z, acc[0][2]))));
            acc[0][3] = fmaf(h0.x, w0.w, fmaf(h0.y, w1.w, fmaf(h0.z, w2v.w, fmaf(h0.w, w3.w, acc[0][3]))));
            acc[1][0] = fmaf(h1.x, w0.x, fmaf(h1.y, w1.x, fmaf(h1.z, w2v.x, fmaf(h1.w, w3.x, acc[1][0]))));
            acc[1][1] = fmaf(h1.x, w0.y, fmaf(h1.y, w1.y, fmaf(h1.z, w2v.y, fmaf(h1.w, w3.y, acc[1][1]))));
            acc[1][2] = fmaf(h1.x, w0.z, fmaf(h1.y, w1.z, fmaf(h1.z, w2v.z, fmaf(h1.w, w3.z, acc[1][2]))));
            acc[1][3] = fmaf(h1.x, w0.w, fmaf(h1.y, w1.w, fmaf(h1.z, w2v.w, fmaf(h1.w, w3.w, acc[1][3]))));
        }
        float4 bb = *(const float4*)(b2 + 4*cg);
        float4 o0 = make_float4(acc[0][0]+bb.x, acc[0][1]+bb.y, acc[0][2]+bb.z, acc[0][3]+bb.w);
        float4 o1 = make_float4(acc[1][0]+bb.x, acc[1][1]+bb.y, acc[1][2]+bb.z, acc[1][3]+bb.w);
        *(float4*)(s_x + r0*64 + 4*cg) = o0;
        *(float4*)(s_x + r1*64 + 4*cg) = o1;
    }
    __syncthreads();

    // --- z1 = silu(ctx @ V1[64:,:] + c1)  (K=64, N=256): 4 cols x 7 rows ---
    {
        const int cg = tid & 63, rg = tid >> 6;   // 64 col-groups, 4 row-groups x 7 rows
        const float* Vp = V1 + 64 * 256 + 4 * cg;
        float acc[7][4];
        #pragma unroll
        for (int r = 0; r < 7; r++)
            #pragma unroll
            for (int c = 0; c < 4; c++) acc[r][c] = 0.f;
        #pragma unroll 2
        for (int k = 0; k < 64; k += 4){
            float4 w0 = *(const float4*)(Vp + (k+0)*256);
            float4 w1 = *(const float4*)(Vp + (k+1)*256);
            float4 w2v = *(const float4*)(Vp + (k+2)*256);
            float4 w3 = *(const float4*)(Vp + (k+3)*256);
            #pragma unroll
            for (int r = 0; r < 7; r++){
                const float4 x4 = *(const float4*)(s_x + (rg*7 + r)*64 + k);
                acc[r][0] = fmaf(x4.x, w0.x, fmaf(x4.y, w1.x, fmaf(x4.z, w2v.x, fmaf(x4.w, w3.x, acc[r][0]))));
                acc[r][1] = fmaf(x4.x, w0.y, fmaf(x4.y, w1.y, fmaf(x4.z, w2v.y, fmaf(x4.w, w3.y, acc[r][1]))));
                acc[r][2] = fmaf(x4.x, w0.z, fmaf(x4.y, w1.z, fmaf(x4.z, w2v.z, fmaf(x4.w, w3.z, acc[r][2]))));
                acc[r][3] = fmaf(x4.x, w0.w, fmaf(x4.y, w1.w, fmaf(x4.z, w2v.w, fmaf(x4.w, w3.w, acc[r][3]))));
            }
        }
        float4 bb = *(const float4*)(c1 + 4*cg);
        #pragma unroll
        for (int r = 0; r < 7; r++){
            float4 o = make_float4(silu_f(acc[r][0]+bb.x), silu_f(acc[r][1]+bb.y),
                                   silu_f(acc[r][2]+bb.z), silu_f(acc[r][3]+bb.w));
            *(float4*)(s_z1 + (rg*7 + r)*256 + 4*cg) = o;
        }
    }
    __syncthreads();

    // --- z2 = silu(z1 @ V2 + c2)  (K=256, N=256): 4 cols x 7 rows ---
    {
        const int cg = tid & 63, rg = tid >> 6;
        const float* Vp = V2 + 4 * cg;
        float acc[7][4];
        #pragma unroll
        for (int r = 0; r < 7; r++)
            #pragma unroll
            for (int c = 0; c < 4; c++) acc[r][c] = 0.f;
        #pragma unroll 2
        for (int k = 0; k < 256; k += 4){
            float4 w0 = *(const float4*)(Vp + (k+0)*256);
            float4 w1 = *(const float4*)(Vp + (k+1)*256);
            float4 w2v = *(const float4*)(Vp + (k+2)*256);
            float4 w3 = *(const float4*)(Vp + (k+3)*256);
            #pragma unroll
            for (int r = 0; r < 7; r++){
                const float4 z4 = *(const float4*)(s_z1 + (rg*7 + r)*256 + k);
                acc[r][0] = fmaf(z4.x, w0.x, fmaf(z4.y, w1.x, fmaf(z4.z, w2v.x, fmaf(z4.w, w3.x, acc[r][0]))));
                acc[r][1] = fmaf(z4.x, w0.y, fmaf(z4.y, w1.y, fmaf(z4.z, w2v.y, fmaf(z4.w, w3.y, acc[r][1]))));
                acc[r][2] = fmaf(z4.x, w0.z, fmaf(z4.y, w1.z, fmaf(z4.z, w2v.z, fmaf(z4.w, w3.z, acc[r][2]))));
                acc[r][3] = fmaf(z4.x, w0.w, fmaf(z4.y, w1.w, fmaf(z4.z, w2v.w, fmaf(z4.w, w3.w, acc[r][3]))));
            }
        }
        float4 bb = *(const float4*)(c2 + 4*cg);
        #pragma unroll
        for (int r = 0; r < 7; r++){
            float4 o = make_float4(silu_f(acc[r][0]+bb.x), silu_f(acc[r][1]+bb.y),
                                   silu_f(acc[r][2]+bb.z), silu_f(acc[r][3]+bb.w));
            *(float4*)(s_z2 + (rg*7 + r)*256 + 4*cg) = o;
        }
    }
    __syncthreads();

    // --- beta_logits = z2 @ V3 + c3  (K=256, N=64): 4 cols x 2 rows (clamped) ---
    {
        const int cg = tid & 15, rg = tid >> 4;
        const float* Vp = V3 + 4 * cg;
        int r0 = rg * 2;     if (r0 > TILE_B - 1) r0 = TILE_B - 1;
        int r1 = rg * 2 + 1; if (r1 > TILE_B - 1) r1 = TILE_B - 1;
        float acc[2][4];
        #pragma unroll
        for (int r = 0; r < 2; r++)
            #pragma unroll
            for (int c = 0; c < 4; c++) acc[r][c] = 0.f;
        #pragma unroll 2
        for (int k = 0; k < 256; k += 4){
            float4 w0 = *(const float4*)(Vp + (k+0)*64);
            float4 w1 = *(const float4*)(Vp + (k+1)*64);
            float4 w2v = *(const float4*)(Vp + (k+2)*64);
            float4 w3 = *(const float4*)(Vp + (k+3)*64);
            const float4 z0 = *(const float4*)(s_z2 + r0*256 + k);
            const float4 z1v = *(const float4*)(s_z2 + r1*256 + k);
            acc[0][0] = fmaf(z0.x, w0.x, fmaf(z0.y, w1.x, fmaf(z0.z, w2v.x, fmaf(z0.w, w3.x, acc[0][0]))));
            acc[0][1] = fmaf(z0.x, w0.y, fmaf(z0.y, w1.y, fmaf(z0.z, w2v.y, fmaf(z0.w, w3.y, acc[0][1]))));
            acc[0][2] = fmaf(z0.x, w0.z, fmaf(z0.y, w1.z, fmaf(z0.z, w2v.z, fmaf(z0.w, w3.z, acc[0][2]))));
            acc[0][3] = fmaf(z0.x, w0.w, fmaf(z0.y, w1.w, fmaf(z0.z, w2v.w, fmaf(z0.w, w3.w, acc[0][3]))));
            acc[1][0] = fmaf(z1v.x, w0.x, fmaf(z1v.y, w1.x, fmaf(z1v.z, w2v.x, fmaf(z1v.w, w3.x, acc[1][0]))));
            acc[1][1] = fmaf(z1v.x, w0.y, fmaf(z1v.y, w1.y, fmaf(z1v.z, w2v.y, fmaf(z1v.w, w3.y, acc[1][1]))));
            acc[1][2] = fmaf(z1v.x, w0.z, fmaf(z1v.y, w1.z, fmaf(z1v.z, w2v.z, fmaf(z1v.w, w3.z, acc[1][2]))));
            acc[1][3] = fmaf(z1v.x, w0.w, fmaf(z1v.y, w1.w, fmaf(z1v.z, w2v.w, fmaf(z1v.w, w3.w, acc[1][3]))));
        }
        float4 bb = *(const float4*)(c3 + 4*cg);
        float4 o0 = make_float4(acc[0][0]+bb.x, acc[0][1]+bb.y, acc[0][2]+bb.z, acc[0][3]+bb.w);
        float4 o1 = make_float4(acc[1][0]+bb.x, acc[1][1]+bb.y, acc[1][2]+bb.z, acc[1][3]+bb.w);
        *(float4*)(s_blog + r0*64 + 4*cg) = o0;
        *(float4*)(s_blog + r1*64 + 4*cg) = o1;
    }
    __syncthreads();

    // --- beta selection + lp_b + final output (clamped slots) ---
    for (int rr = 0; rr < 4; ++rr){
        int rloc = wid * 4 + rr;
        if (rloc > TILE_B - 1) rloc = TILE_B - 1;
        int row = row0 + rloc;
        if (row > NB - 1) row = NB - 1;
        const float* lg = s_blog + rloc * 64;
        float l0 = lg[lane], l1 = lg[lane + 32];
        float mv = fmaxf(l0, l1);
        #pragma unroll
        for (int off = 16; off > 0; off >>= 1)
            mv = fmaxf(mv, __shfl_xor_sync(0xffffffffu, mv, off));
        float zv = expf(l0 - mv) + expf(l1 - mv);
        #pragma unroll
        for (int off = 16; off > 0; off >>= 1)
            zv += __shfl_xor_sync(0xffffffffu, zv, off);
        int sel[5];
        float lpb = row_topk_lp(Ub + (size_t)row * 64, lg, mv, zv,
                                out + (size_t)row * 128 + 64, lane, sel);
        if (lane == 0)
            out[(size_t)NB * 128 + row] = s_lpa[rloc] + lpb;
    }
}

extern "C" void kernel_launch(void* const* d_in, const int* in_sizes, int n_in,
                              void* d_out, int out_size)
{
    (void)in_sizes; (void)n_in; (void)out_size;
    const float* Ua = (const float*)d_in[0];
    const float* Ub = (const float*)d_in[1];
    const float* AL = (const float*)d_in[2];
    const float* W1 = (const float*)d_in[3];
    const float* b1 = (const float*)d_in[4];
    const float* W2 = (const float*)d_in[5];
    const float* b2 = (const float*)d_in[6];
    const float* V1 = (const float*)d_in[7];
    const float* c1 = (const float*)d_in[8];
    const float* V2 = (const float*)d_in[9];
    const float* c2 = (const float*)d_in[10];
    const float* V3 = (const float*)d_in[11];
    const float* c3 = (const float*)d_in[12];
    float* out = (float*)d_out;

    const int smem_bytes = SMEM_FLOATS * (int)sizeof(float);
    cudaFuncSetAttribute(pcf_kernel, cudaFuncAttributeMaxDynamicSharedMemorySize, smem_bytes);
    pcf_kernel<<<GRID, NT, smem_bytes>>>(Ua, Ub, AL, W1, b1, W2, b2,
                                         V1, c1, V2, c2, V3, c3, out);
}

// round 9
// speedup vs baseline: 1.5515x; 1.3455x over previous
#include <cuda_runtime.h>
#include <math.h>
#include <stdint.h>

#define NB      8192
#define TILE_B  28
#define NT      256
#define GRID    293
#define MPAD    32           // padded M for mma (2 x m16 tiles)

// padded leading dims (all == 4 mod 32 -> conflict-free fragment LDS)
#define LDH 132
#define LDX 68
#define LDZ 260
#define LDB 68

// smem layout (floats): header 240 | h 32x132 | x 32x68 | z1 32x260 | z2 32x260 | blog 32x68
#define OFF_H    240
#define OFF_X    4464
#define OFF_Z1   6640
#define OFF_Z2   14960
#define OFF_BLOG 23280
#define SMEM_FLOATS 25456

__device__ __forceinline__ float silu_f(float x){
    return x * (1.0f / (1.0f + __expf(-x)));
}

// m16n8k8 tf32 mma: D += A*B (fp32 accum). Raw fp32 bits as tf32 (HW truncation).
__device__ __forceinline__ void mma_tf32(float* d, const uint32_t* a, uint32_t b0, uint32_t b1){
    asm volatile(
        "mma.sync.aligned.m16n8k8.row.col.f32.tf32.tf32.f32 "
        "{%0,%1,%2,%3}, {%4,%5,%6,%7}, {%8,%9}, {%0,%1,%2,%3};"
        : "+f"(d[0]), "+f"(d[1]), "+f"(d[2]), "+f"(d[3])
        : "r"(a[0]), "r"(a[1]), "r"(a[2]), "r"(a[3]), "r"(b0), "r"(b1));
}

// Generic warp-level GEMM phase: D[MPAD x (8*NTILES*8warps)] = A[MPAD x K] * B[K x N] + bias
// A in smem (lda), B in gmem row-major [K x LDN], D to smem (ldd). Optional silu.
template<int KSTEPS, int NTILES, int LDA_, int LDN_, int LDD_, bool DOSILU>
__device__ __forceinline__ void mma_phase(const float* __restrict__ As,
                                          const float* __restrict__ Bg,
                                          const float* __restrict__ bias,
                                          float* __restrict__ Ds,
                                          int wid, int lane)
{
    const int gid = lane >> 2, tig = lane & 3;
    const int n0 = wid * (NTILES * 8);
    float d[2][NTILES][4];
    #pragma unroll
    for (int rt = 0; rt < 2; rt++)
        #pragma unroll
        for (int nt = 0; nt < NTILES; nt++)
            #pragma unroll
            for (int i = 0; i < 4; i++) d[rt][nt][i] = 0.f;

    #pragma unroll 4
    for (int ks = 0; ks < KSTEPS; ks++){
        const int k0 = ks * 8;
        uint32_t a[2][4];
        #pragma unroll
        for (int rt = 0; rt < 2; rt++){
            const int r = gid + 16 * rt;
            a[rt][0] = __float_as_uint(As[r       * LDA_ + k0 + tig]);
            a[rt][1] = __float_as_uint(As[(r + 8) * LDA_ + k0 + tig]);
            a[rt][2] = __float_as_uint(As[r       * LDA_ + k0 + tig + 4]);
            a[rt][3] = __float_as_uint(As[(r + 8) * LDA_ + k0 + tig + 4]);
        }
        #pragma unroll
        for (int nt = 0; nt < NTILES; nt++){
            const float* Bp = Bg + (size_t)(k0 + tig) * LDN_ + n0 + nt * 8 + gid;
            uint32_t b0 = __float_as_uint(Bp[0]);
            uint32_t b1 = __float_as_uint(Bp[4 * LDN_]);
            mma_tf32(d[0][nt], a[0], b0, b1);
            mma_tf32(d[1][nt], a[1], b0, b1);
        }
    }
    #pragma unroll
    for (int rt = 0; rt < 2; rt++){
        #pragma unroll
        for (int nt = 0; nt < NTILES; nt++){
            const int r = gid + 16 * rt;
            const int c = n0 + nt * 8 + 2 * tig;
            const float bx = bias[c], by = bias[c + 1];
            float v0 = d[rt][nt][0] + bx, v1 = d[rt][nt][1] + by;
            float v2 = d[rt][nt][2] + bx, v3 = d[rt][nt][3] + by;
            if (DOSILU){ v0 = silu_f(v0); v1 = silu_f(v1); v2 = silu_f(v2); v3 = silu_f(v3); }
            *reinterpret_cast<float2*>(Ds + r       * LDD_ + c) = make_float2(v0, v1);
            *reinterpret_cast<float2*>(Ds + (r + 8) * LDD_ + c) = make_float2(v2, v3);
        }
    }
}

// Warp-cooperative top-6 of 64 values (2 per lane). Tie-break: lower index.
__device__ __forceinline__ void topk6(float p0, float p1, int lane, int* sel, float* sv){
    #pragma unroll
    for (int t = 0; t < 6; ++t){
        float v = p0; int id = lane;
        if (p1 > v){ v = p1; id = lane + 32; }
        #pragma unroll
        for (int off = 16; off > 0; off >>= 1){
            float ov = __shfl_xor_sync(0xffffffffu, v, off);
            int  oid = __shfl_xor_sync(0xffffffffu, id, off);
            if (ov > v || (ov == v && oid < id)){ v = ov; id = oid; }
        }
        sv[t] = v; sel[t] = id;
        if (id == lane)           p0 = -INFINITY;
        else if (id == lane + 32) p1 = -INFINITY;
    }
}

// One row: gumbel perturb, top-5 select, one-hot write, exact-PL log-prob.
__device__ float row_topk_lp(const float* __restrict__ u,
                             const float* __restrict__ lg,
                             float m, float Z,
                             float* __restrict__ cfg,
                             int lane, int* selOut)
{
    float l0 = lg[lane], l1 = lg[lane + 32];
    float u0 = fmaxf(u[lane],      1e-10f);
    float u1 = fmaxf(u[lane + 32], 1e-10f);
    float p0 = l0 - __logf(-__logf(u0));
    float p1 = l1 - __logf(-__logf(u1));
    int sel[6]; float sv[6];
    topk6(p0, p1, lane, sel, sv);
    if (sv[4] - sv[5] < 1e-4f){
        p0 = l0 - (float)log(-log((double)u0));
        p1 = l1 - (float)log(-log((double)u1));
        topk6(p0, p1, lane, sel, sv);
    }
    float c0 = 0.f, c1 = 0.f;
    #pragma unroll
    for (int t = 0; t < 5; ++t){
        c0 += (sel[t] == lane)      ? 1.f : 0.f;
        c1 += (sel[t] == lane + 32) ? 1.f : 0.f;
    }
    cfg[lane]      = c0;
    cfg[lane + 32] = c1;

    // exact PL over 5! orderings via 2^5-subset DP
    float lsum = 0.f, e[5];
    #pragma unroll
    for (int t = 0; t < 5; ++t){
        float lt = lg[sel[t]];
        lsum += lt;
        e[t] = expf(lt - m);
    }
    float f[32];
    f[31] = 1.f;
    #pragma unroll
    for (int mask = 30; mask >= 0; --mask){
        float Em = 0.f, s = 0.f;
        #pragma unroll
        for (int t = 0; t < 5; ++t){
            if (mask & (1 << t)) Em += e[t];
            else                 s  += f[mask | (1 << t)];
        }
        f[mask] = __fdividef(s, Z - Em);
    }
    #pragma unroll
    for (int t = 0; t < 5; ++t) selOut[t] = sel[t];
    return lsum - 5.f * m + logf(f[0]);
}

__global__ __launch_bounds__(NT, 2)
void pcf_kernel(const float* __restrict__ Ua, const float* __restrict__ Ub,
                const float* __restrict__ AL,
                const float* __restrict__ W1, const float* __restrict__ b1,
                const float* __restrict__ W2, const float* __restrict__ b2,
                const float* __restrict__ V1, const float* __restrict__ c1,
                const float* __restrict__ V2, const float* __restrict__ c2,
                const float* __restrict__ V3, const float* __restrict__ c3,
                float* __restrict__ out)
{
    extern __shared__ float sm[];
    float* s_alog = sm;                    // 64
    float* s_scal = sm + 64;               // 4
    int*   s_sela = (int*)(sm + 68);       // 140 (28 rows x 5)
    float* s_lpa  = sm + 208;              // 28 -> header ends 240
    float* s_h    = sm + OFF_H;            // 32 x LDH (pad rows zero)
    float* s_x    = sm + OFF_X;            // 32 x LDX
    float* s_z1   = sm + OFF_Z1;           // 32 x LDZ
    float* s_z2   = sm + OFF_Z2;           // 32 x LDZ
    float* s_blog = sm + OFF_BLOG;         // 32 x LDB

    const int tid  = threadIdx.x;
    const int lane = tid & 31;
    const int wid  = tid >> 5;             // 0..7
    const int row0 = blockIdx.x * TILE_B;

    // --- alpha logits stats (block-constant) ---
    if (wid == 0){
        float l0 = AL[lane], l1 = AL[lane + 32];
        s_alog[lane] = l0; s_alog[lane + 32] = l1;
        float mv = fmaxf(l0, l1);
        #pragma unroll
        for (int off = 16; off > 0; off >>= 1)
            mv = fmaxf(mv, __shfl_xor_sync(0xffffffffu, mv, off));
        float zv = expf(l0 - mv) + expf(l1 - mv);
        #pragma unroll
        for (int off = 16; off > 0; off >>= 1)
            zv += __shfl_xor_sync(0xffffffffu, zv, off);
        if (lane == 0){ s_scal[0] = mv; s_scal[1] = zv; }
    }
    __syncthreads();
    const float ma = s_scal[0], Za = s_scal[1];

    // --- alpha selection + lp_a (8 warps x 4 slots, clamped) ---
    for (int rr = 0; rr < 4; ++rr){
        int rloc = wid * 4 + rr;
        if (rloc > TILE_B - 1) rloc = TILE_B - 1;
        int row = row0 + rloc;
        if (row > NB - 1) row = NB - 1;
        int sel[5];
        float lp = row_topk_lp(Ua + (size_t)row * 64, s_alog, ma, Za,
                               out + (size_t)row * 128, lane, sel);
        if (lane == 0){
            s_lpa[rloc] = lp;
            #pragma unroll
            for (int t = 0; t < 5; ++t) s_sela[rloc * 5 + t] = sel[t];
        }
    }
    __syncthreads();

    // --- h = silu(sum of 5 W1 rows + b1), rows 28..31 zero-padded ---
    for (int i = tid; i < MPAD * 128; i += NT){
        int r = i >> 7, j = i & 127;
        float v = 0.f;
        if (r < TILE_B){
            float a = b1[j];
            #pragma unroll
            for (int t = 0; t < 5; ++t) a += W1[s_sela[r * 5 + t] * 128 + j];
            v = silu_f(a);
        }
        s_h[r * LDH + j] = v;
    }
    __syncthreads();

    // --- ctx = h @ W2 + b2  (M=32, N=64, K=128) ---
    mma_phase<16, 1, LDH, 64, LDX, false>(s_h, W2, b2, s_x, wid, lane);
    __syncthreads();

    // --- z1 = silu(ctx @ V1[64:,:] + c1)  (M=32, N=256, K=64) ---
    mma_phase<8, 4, LDX, 256, LDZ, true>(s_x, V1 + 64 * 256, c1, s_z1, wid, lane);
    __syncthreads();

    // --- z2 = silu(z1 @ V2 + c2)  (M=32, N=256, K=256) ---
    mma_phase<32, 4, LDZ, 256, LDZ, true>(s_z1, V2, c2, s_z2, wid, lane);
    __syncthreads();

    // --- beta_logits = z2 @ V3 + c3  (M=32, N=64, K=256) ---
    mma_phase<32, 1, LDZ, 64, LDB, false>(s_z2, V3, c3, s_blog, wid, lane);
    __syncthreads();

    // --- beta selection + lp_b + final output (clamped slots) ---
    for (int rr = 0; rr < 4; ++rr){
        int rloc = wid * 4 + rr;
        if (rloc > TILE_B - 1) rloc = TILE_B - 1;
        int row = row0 + rloc;
        if (row > NB - 1) row = NB - 1;
        const float* lg = s_blog + rloc * LDB;
        float l0 = lg[lane], l1 = lg[lane + 32];
        float mv = fmaxf(l0, l1);
        #pragma unroll
        for (int off = 16; off > 0; off >>= 1)
            mv = fmaxf(mv, __shfl_xor_sync(0xffffffffu, mv, off));
        float zv = expf(l0 - mv) + expf(l1 - mv);
        #pragma unroll
        for (int off = 16; off > 0; off >>= 1)
            zv += __shfl_xor_sync(0xffffffffu, zv, off);
        int sel[5];
        float lpb = row_topk_lp(Ub + (size_t)row * 64, lg, mv, zv,
                                out + (size_t)row * 128 + 64, lane, sel);
        if (lane == 0)
            out[(size_t)NB * 128 + row] = s_lpa[rloc] + lpb;
    }
}

extern "C" void kernel_launch(void* const* d_in, const int* in_sizes, int n_in,
                              void* d_out, int out_size)
{
    (void)in_sizes; (void)n_in; (void)out_size;
    const float* Ua = (const float*)d_in[0];
    const float* Ub = (const float*)d_in[1];
    const float* AL = (const float*)d_in[2];
    const float* W1 = (const float*)d_in[3];
    const float* b1 = (const float*)d_in[4];
    const float* W2 = (const float*)d_in[5];
    const float* b2 = (const float*)d_in[6];
    const float* V1 = (const float*)d_in[7];
    const float* c1 = (const float*)d_in[8];
    const float* V2 = (const float*)d_in[9];
    const float* c2 = (const float*)d_in[10];
    const float* V3 = (const float*)d_in[11];
    const float* c3 = (const float*)d_in[12];
    float* out = (float*)d_out;

    const int smem_bytes = SMEM_FLOATS * (int)sizeof(float);
    cudaFuncSetAttribute(pcf_kernel, cudaFuncAttributeMaxDynamicSharedMemorySize, smem_bytes);
    pcf_kernel<<<GRID, NT, smem_bytes>>>(Ua, Ub, AL, W1, b1, W2, b2,
                                         V1, c1, V2, c2, V3, c3, out);
}